// round 1
// baseline (speedup 1.0000x reference)
#include <cuda_runtime.h>
#include <math.h>

// Per-row KLD loss between two rotated boxes expressed as 2D Gaussians.
// All 2x2 matrix algebra reduced to closed-form scalars.
__device__ __forceinline__ float row_loss(const float* __restrict__ p,
                                          const float* __restrict__ t) {
    // deltas between means
    float dx = p[0] - t[0];
    float dy = p[1] - t[1];

    // pred sigma
    float wp = fminf(fmaxf(p[2], 1e-7f), 1e7f);
    float hp = fminf(fmaxf(p[3], 1e-7f), 1e7f);
    float ap = 0.25f * wp * wp;          // (w/2)^2
    float bp = 0.25f * hp * hp;
    float sp, cp;
    sincosf(p[4], &sp, &cp);
    float cp2 = cp * cp, sp2 = sp * sp;
    float p00 = ap * cp2 + bp * sp2;
    float p11 = ap * sp2 + bp * cp2;
    float p01 = (ap - bp) * sp * cp;

    // target sigma
    float wt = fminf(fmaxf(t[2], 1e-7f), 1e7f);
    float ht = fminf(fmaxf(t[3], 1e-7f), 1e7f);
    float at = 0.25f * wt * wt;
    float bt = 0.25f * ht * ht;
    float st, ct;
    sincosf(t[4], &st, &ct);
    float ct2 = ct * ct, st2 = st * st;
    float t00 = at * ct2 + bt * st2;
    float t11 = at * st2 + bt * ct2;
    float t01 = (at - bt) * st * ct;

    float det_p = p00 * p11 - p01 * p01;
    float det_t = t00 * t11 - t01 * t01;
    float inv_det_t = 1.0f / det_t;

    // term1 = delta^T Sigma_t^{-1} delta
    float term1 = (dx * dx * t11 - 2.0f * dx * dy * t01 + dy * dy * t00) * inv_det_t;
    // tr(Sigma_t^{-1} Sigma_p)
    float tr = (t11 * p00 + t00 * p11 - 2.0f * t01 * p01) * inv_det_t;

    float dis = term1 + tr + logf(det_t / det_p) - 2.0f;
    float kl = fmaxf(dis, 1e-6f);
    return 1.0f - 1.0f / (1.0f + log1pf(kl));
}

// Vectorized: each thread handles 4 rows = 20 floats = 5 float4 loads per input.
__global__ void kld_loss_vec4_kernel(const float4* __restrict__ pred,
                                     const float4* __restrict__ targ,
                                     float4* __restrict__ out, int n4) {
    int i = blockIdx.x * blockDim.x + threadIdx.x;
    if (i >= n4) return;

    float4 pv[5], tv[5];
#pragma unroll
    for (int k = 0; k < 5; k++) {
        pv[k] = pred[5 * i + k];
        tv[k] = targ[5 * i + k];
    }
    const float* pf = reinterpret_cast<const float*>(pv);
    const float* tf = reinterpret_cast<const float*>(tv);

    float4 r;
    r.x = row_loss(pf + 0,  tf + 0);
    r.y = row_loss(pf + 5,  tf + 5);
    r.z = row_loss(pf + 10, tf + 10);
    r.w = row_loss(pf + 15, tf + 15);
    out[i] = r;
}

// Scalar tail for n % 4 != 0 (not hit for N=4M, kept for safety).
__global__ void kld_loss_tail_kernel(const float* __restrict__ pred,
                                     const float* __restrict__ targ,
                                     float* __restrict__ out,
                                     int start, int n) {
    int i = start + blockIdx.x * blockDim.x + threadIdx.x;
    if (i >= n) return;
    out[i] = row_loss(pred + 5 * i, targ + 5 * i);
}

extern "C" void kernel_launch(void* const* d_in, const int* in_sizes, int n_in,
                              void* d_out, int out_size) {
    const float* pred = (const float*)d_in[0];
    const float* targ = (const float*)d_in[1];
    float* out = (float*)d_out;

    int n = in_sizes[0] / 5;   // number of rows
    int n4 = n / 4;
    int rem_start = n4 * 4;

    if (n4 > 0) {
        const int threads = 256;
        int blocks = (n4 + threads - 1) / threads;
        kld_loss_vec4_kernel<<<blocks, threads>>>(
            (const float4*)pred, (const float4*)targ, (float4*)out, n4);
    }
    if (rem_start < n) {
        int rem = n - rem_start;
        kld_loss_tail_kernel<<<(rem + 127) / 128, 128>>>(pred, targ, out,
                                                         rem_start, n);
    }
}